// round 1
// baseline (speedup 1.0000x reference)
#include <cuda_runtime.h>
#include <math.h>
#include <stdint.h>

#define NROWS 65536
#define DIMV  512
#define CD    10
#define NQ    8
#define OUT_ELEMS   (NROWS * DIMV)           // 33554432
#define IDX_ELEMS   (NROWS * NQ)             // 524288
#define LOSS_OFFSET (OUT_ELEMS + IDX_ELEMS)  // 34078720

// Scratch (static __device__ arrays — no runtime allocation)
__device__ float g_ptab[(size_t)NQ * NROWS * CD];  // [q][row][d] Bernoulli p
__device__ float g_codesum[NQ * 1024];             // sum over rows of p_c
__device__ float g_psent[NQ];
__device__ float g_commit[NQ];

// ---------------------------------------------------------------------------
__global__ void k_zero() {
    int t = blockIdx.x * blockDim.x + threadIdx.x;
    if (t < NQ * 1024) g_codesum[t] = 0.f;
    if (t < NQ) { g_psent[t] = 0.f; g_commit[t] = 0.f; }
}

// ---------------------------------------------------------------------------
// Main fused kernel: h = x@w_in + b_in ; 8x LFQ pipeline ; out = qo@w_out + b_out
// Warp processes 4 rows per iteration.
__global__ void __launch_bounds__(128, 4) k_main(
    const float* __restrict__ x,
    const float* __restrict__ w_in,
    const float* __restrict__ b_in,
    const float* __restrict__ w_out,
    const float* __restrict__ b_out,
    float* __restrict__ out,
    float* __restrict__ out_idx)
{
    // shared staging: w_in padded stride 11 (conflict-free LDS), w_out, b_out, b_in
    __shared__ __align__(16) float ws[DIMV * 11];
    __shared__ __align__(16) float wos[CD * DIMV];
    __shared__ __align__(16) float bs[DIMV];
    __shared__ float bis[16];

    int tid = threadIdx.x;
    for (int i = tid; i < DIMV; i += 128) {
        #pragma unroll
        for (int d = 0; d < CD; d++) ws[i * 11 + d] = w_in[i * CD + d];
        bs[i] = b_out[i];
    }
    for (int i = tid; i < CD * DIMV; i += 128) wos[i] = w_out[i];
    if (tid < CD) bis[tid] = b_in[tid];
    __syncthreads();

    const int lane = tid & 31;
    const int gwarp = blockIdx.x * 4 + (tid >> 5);   // 4096 warps total
    const unsigned FULL = 0xffffffffu;

    float psent[NQ], commit[NQ];
    #pragma unroll
    for (int q = 0; q < NQ; q++) { psent[q] = 0.f; commit[q] = 0.f; }

    for (int quad = gwarp; quad < NROWS / 4; quad += 4096) {
        const int row0 = quad * 4;
        const float* xr = x + (size_t)row0 * DIMV;

        // ---- h = x @ w_in (partials per lane over strided columns) ----
        float h[4][CD];
        #pragma unroll
        for (int m = 0; m < 4; m++)
            #pragma unroll
            for (int d = 0; d < CD; d++) h[m][d] = 0.f;

        #pragma unroll
        for (int k = 0; k < 16; k++) {
            int col = k * 32 + lane;
            float x0 = xr[col];
            float x1 = xr[DIMV + col];
            float x2 = xr[2 * DIMV + col];
            float x3 = xr[3 * DIMV + col];
            #pragma unroll
            for (int d = 0; d < CD; d++) {
                float w = ws[col * 11 + d];
                h[0][d] = fmaf(x0, w, h[0][d]);
                h[1][d] = fmaf(x1, w, h[1][d]);
                h[2][d] = fmaf(x2, w, h[2][d]);
                h[3][d] = fmaf(x3, w, h[3][d]);
            }
        }
        // butterfly reduce: every lane ends with full sums
        #pragma unroll
        for (int m = 0; m < 4; m++)
            #pragma unroll
            for (int d = 0; d < CD; d++)
                #pragma unroll
                for (int off = 16; off > 0; off >>= 1)
                    h[m][d] += __shfl_xor_sync(FULL, h[m][d], off);

        // lane d takes dim d of each row
        float r0 = 0.f, r1 = 0.f, r2 = 0.f, r3 = 0.f;
        #pragma unroll
        for (int d = 0; d < CD; d++) {
            if (lane == d) { r0 = h[0][d]; r1 = h[1][d]; r2 = h[2][d]; r3 = h[3][d]; }
        }
        float bi = (lane < CD) ? bis[lane] : 0.f;
        r0 += bi; r1 += bi; r2 += bi; r3 += bi;

        // ---- LFQ pipeline: lane = dim; ballot for index bits ----
        float qo0 = 0.f, qo1 = 0.f, qo2 = 0.f, qo3 = 0.f;
        float iv0 = 0.f, iv1 = 0.f, iv2 = 0.f, iv3 = 0.f;

        #pragma unroll
        for (int q = 0; q < NQ; q++) {
            const float scale = 1.0f / (float)(1 << q);

            #define QSTEP(RM, QOM, IVM, MI)                                              \
            {                                                                            \
                bool pos = (RM) > 0.f;                                                   \
                unsigned bl = __ballot_sync(FULL, pos) & 0x3FFu;                         \
                int idx = (int)(__brev(bl) >> 22);                                       \
                if (lane == q) (IVM) = (float)idx;                                       \
                float qv = pos ? scale : -scale;                                         \
                float dlt = (RM) - qv;                                                   \
                float a = 400.f * scale * (RM);                                          \
                float p = 1.f / (1.f + expf(-a));                                        \
                if (lane < CD) {                                                         \
                    commit[q] += dlt * dlt;                                              \
                    float pm = 1.f - p;                                                  \
                    psent[q] -= p * logf(fmaxf(p, 1e-20f))                               \
                              + pm * logf(fmaxf(pm, 1e-20f));                            \
                    g_ptab[((size_t)q * NROWS + (row0 + MI)) * CD + lane] = p;           \
                }                                                                        \
                (RM) = dlt;                                                              \
                (QOM) += qv;                                                             \
            }

            QSTEP(r0, qo0, iv0, 0)
            QSTEP(r1, qo1, iv1, 1)
            QSTEP(r2, qo2, iv2, 2)
            QSTEP(r3, qo3, iv3, 3)
            #undef QSTEP
        }

        // ---- indices out (lane q writes its quantizer's value) ----
        if (lane < NQ) {
            out_idx[(size_t)(row0 + 0) * NQ + lane] = iv0;
            out_idx[(size_t)(row0 + 1) * NQ + lane] = iv1;
            out_idx[(size_t)(row0 + 2) * NQ + lane] = iv2;
            out_idx[(size_t)(row0 + 3) * NQ + lane] = iv3;
        }

        // ---- out = qo @ w_out + b_out, 2 rows at a time (amortize w LDS) ----
        float* outp = out + (size_t)row0 * DIMV;
        #pragma unroll
        for (int pr = 0; pr < 2; pr++) {
            float qa = pr ? qo2 : qo0;
            float qb = pr ? qo3 : qo1;
            float sa[CD], sb[CD];
            #pragma unroll
            for (int d = 0; d < CD; d++) {
                sa[d] = __shfl_sync(FULL, qa, d);
                sb[d] = __shfl_sync(FULL, qb, d);
            }
            #pragma unroll
            for (int k = 0; k < 4; k++) {
                int j4 = k * 32 + lane;
                float4 b4 = ((const float4*)bs)[j4];
                float4 aA = b4, aB = b4;
                #pragma unroll
                for (int d = 0; d < CD; d++) {
                    float4 w4 = ((const float4*)wos)[d * 128 + j4];
                    aA.x = fmaf(sa[d], w4.x, aA.x);
                    aA.y = fmaf(sa[d], w4.y, aA.y);
                    aA.z = fmaf(sa[d], w4.z, aA.z);
                    aA.w = fmaf(sa[d], w4.w, aA.w);
                    aB.x = fmaf(sb[d], w4.x, aB.x);
                    aB.y = fmaf(sb[d], w4.y, aB.y);
                    aB.z = fmaf(sb[d], w4.z, aB.z);
                    aB.w = fmaf(sb[d], w4.w, aB.w);
                }
                ((float4*)(outp + (size_t)(2 * pr) * DIMV))[j4] = aA;
                ((float4*)(outp + (size_t)(2 * pr + 1) * DIMV))[j4] = aB;
            }
        }
    }

    // ---- reduce per-warp loss partials, one atomic per (warp, q) ----
    #pragma unroll
    for (int q = 0; q < NQ; q++) {
        float v = psent[q], c = commit[q];
        #pragma unroll
        for (int off = 16; off > 0; off >>= 1) {
            v += __shfl_xor_sync(FULL, v, off);
            c += __shfl_xor_sync(FULL, c, off);
        }
        if (lane == 0) {
            atomicAdd(&g_psent[q], v);
            atomicAdd(&g_commit[q], c);
        }
    }
}

// ---------------------------------------------------------------------------
// Codebook avg_prob accumulation: p_c = hi[c>>5] * lo[c&31]; 1 FFMA per (row,code)
__global__ void __launch_bounds__(256) k_code() {
    const int q = blockIdx.x >> 6;        // 64 row-chunks per quantizer
    const int chunk = blockIdx.x & 63;
    const int row0 = chunk * 1024;
    const int t = threadIdx.x;

    __shared__ float ps_s[16][CD];
    __shared__ __align__(16) float hl[16][64];   // [row][hi(0..31) | lo(32..63)]

    float acc0 = 0.f, acc1 = 0.f, acc2 = 0.f, acc3 = 0.f;
    const int hi_idx = t >> 3;           // 0..31
    const int lo0 = (t & 7) * 4;         // 0..28

    const float* pt = g_ptab + (size_t)q * NROWS * CD;

    for (int tile = 0; tile < 64; tile++) {
        int r0 = row0 + tile * 16;
        if (t < 160) ps_s[t / CD][t % CD] = pt[(size_t)(r0 + t / CD) * CD + (t % CD)];
        __syncthreads();

        // each thread builds 4 consecutive hi OR lo partial products for one row
        {
            int rl = t >> 4;
            int v0 = (t & 15) * 4;
            bool isHi = (v0 < 32);
            int dbase = isHi ? 0 : 5;
            int vb = isHi ? v0 : (v0 - 32);
            float p0 = ps_s[rl][dbase + 0], p1 = ps_s[rl][dbase + 1];
            float p2 = ps_s[rl][dbase + 2], p3 = ps_s[rl][dbase + 3];
            float p4 = ps_s[rl][dbase + 4];
            float n0 = 1.f - p0, n1 = 1.f - p1, n2 = 1.f - p2, n3 = 1.f - p3, n4 = 1.f - p4;
            float4 res;
            float* rp = &res.x;
            #pragma unroll
            for (int j = 0; j < 4; j++) {
                int v = vb + j;
                float val = ((v & 16) ? p0 : n0);
                val *= ((v & 8) ? p1 : n1);
                val *= ((v & 4) ? p2 : n2);
                val *= ((v & 2) ? p3 : n3);
                val *= ((v & 1) ? p4 : n4);
                rp[j] = val;
            }
            *(float4*)&hl[rl][v0] = res;
        }
        __syncthreads();

        #pragma unroll
        for (int rl = 0; rl < 16; rl++) {
            float hv = hl[rl][hi_idx];
            float4 l4 = *(const float4*)&hl[rl][32 + lo0];
            acc0 = fmaf(hv, l4.x, acc0);
            acc1 = fmaf(hv, l4.y, acc1);
            acc2 = fmaf(hv, l4.z, acc2);
            acc3 = fmaf(hv, l4.w, acc3);
        }
        __syncthreads();
    }

    int c = q * 1024 + hi_idx * 32 + lo0;
    atomicAdd(&g_codesum[c + 0], acc0);
    atomicAdd(&g_codesum[c + 1], acc1);
    atomicAdd(&g_codesum[c + 2], acc2);
    atomicAdd(&g_codesum[c + 3], acc3);
}

// ---------------------------------------------------------------------------
__global__ void k_fin(float* __restrict__ loss_out) {
    __shared__ float red[256];
    int t = threadIdx.x;
    for (int q = 0; q < NQ; q++) {
        float e = 0.f;
        for (int c = t; c < 1024; c += 256) {
            float avg = g_codesum[q * 1024 + c] * (1.0f / (float)NROWS);
            e -= avg * logf(fmaxf(avg, 1e-20f));
        }
        red[t] = e;
        __syncthreads();
        for (int s = 128; s > 0; s >>= 1) {
            if (t < s) red[t] += red[t + s];
            __syncthreads();
        }
        if (t == 0) {
            float per_sample = g_psent[q] * (1.0f / (float)NROWS);
            float ent_aux = per_sample - red[0];               // gamma = 1.0
            float commit = g_commit[q] * (1.0f / (float)(NROWS * CD));
            loss_out[q] = ent_aux * 0.1f + commit * 0.25f;
        }
        __syncthreads();
    }
}

// ---------------------------------------------------------------------------
extern "C" void kernel_launch(void* const* d_in, const int* in_sizes, int n_in,
                              void* d_out, int out_size) {
    const float* x     = (const float*)d_in[0];
    const float* w_in  = (const float*)d_in[1];
    const float* b_in  = (const float*)d_in[2];
    const float* w_out = (const float*)d_in[3];
    const float* b_out = (const float*)d_in[4];

    float* out   = (float*)d_out;
    float* idx   = out + OUT_ELEMS;
    float* loss  = out + LOSS_OFFSET;

    k_zero<<<32, 256>>>();
    k_main<<<1024, 128>>>(x, w_in, b_in, w_out, b_out, out, idx);
    k_code<<<512, 256>>>();
    k_fin<<<1, 256>>>(loss);
}

// round 2
// speedup vs baseline: 1.1049x; 1.1049x over previous
#include <cuda_runtime.h>
#include <math.h>
#include <stdint.h>

#define NROWS 65536
#define DIMV  512
#define CD    10
#define NQ    8
#define OUT_ELEMS   (NROWS * DIMV)
#define IDX_ELEMS   (NROWS * NQ)
#define LOSS_OFFSET (OUT_ELEMS + IDX_ELEMS)

__device__ float g_ptab[(size_t)NQ * NROWS * CD];
__device__ float g_codesum[NQ * 1024];
__device__ float g_psent[NQ];
__device__ float g_commit[NQ];

// ---------------------------------------------------------------------------
__global__ void k_zero() {
    int t = blockIdx.x * blockDim.x + threadIdx.x;
    if (t < NQ * 1024) g_codesum[t] = 0.f;
    if (t < NQ) { g_psent[t] = 0.f; g_commit[t] = 0.f; }
}

// ---------------------------------------------------------------------------
// Fused: h = x@w_in + b_in ; 8x LFQ pipeline ; out = qo@w_out + b_out
// Warp processes 4 rows/iter. Half-warp 0 owns rows {0,1}, half-warp 1 rows {2,3}.
__global__ void __launch_bounds__(128, 2) k_main(
    const float* __restrict__ x,
    const float* __restrict__ w_in,
    const float* __restrict__ b_in,
    const float* __restrict__ w_out,
    const float* __restrict__ b_out,
    float* __restrict__ out,
    float* __restrict__ out_idx)
{
    __shared__ __align__(16) float ws[DIMV * 11];   // w_in padded (conflict-free)
    __shared__ __align__(16) float wos[CD * DIMV];  // w_out
    __shared__ __align__(16) float bs[DIMV];        // b_out
    __shared__ float bis[16];                       // b_in

    int tid = threadIdx.x;
    for (int i = tid; i < DIMV; i += 128) {
        #pragma unroll
        for (int d = 0; d < CD; d++) ws[i * 11 + d] = w_in[i * CD + d];
        bs[i] = b_out[i];
    }
    for (int i = tid; i < CD * DIMV; i += 128) wos[i] = w_out[i];
    if (tid < CD) bis[tid] = b_in[tid];
    __syncthreads();

    const int lane = tid & 31;
    const int half = lane >> 4;      // 0 -> rows 0,1 ; 1 -> rows 2,3
    const int hl   = lane & 15;
    const int gwarp = blockIdx.x * 4 + (tid >> 5);
    const unsigned FULL = 0xffffffffu;

    float psent[NQ], commit[NQ];
    #pragma unroll
    for (int q = 0; q < NQ; q++) { psent[q] = 0.f; commit[q] = 0.f; }

    for (int quad = gwarp; quad < NROWS / 4; quad += 4096) {
        const int row0 = quad * 4;
        const float* xra = x + (size_t)(row0 + 2 * half) * DIMV;      // row 0 or 2
        const float* xrb = xra + DIMV;                                 // row 1 or 3

        // ---- h partial sums: each half-warp covers cols via 16-lane stride ----
        float h[2][CD];
        #pragma unroll
        for (int m = 0; m < 2; m++)
            #pragma unroll
            for (int d = 0; d < CD; d++) h[m][d] = 0.f;

        #pragma unroll
        for (int k = 0; k < 16; k++) {
            int col = k * 32 + hl * 2;
            float2 xa = *(const float2*)(xra + col);
            float2 xb = *(const float2*)(xrb + col);
            #pragma unroll
            for (int d = 0; d < CD; d++) {
                float w0 = ws[col * 11 + d];
                float w1 = ws[(col + 1) * 11 + d];
                h[0][d] = fmaf(xa.x, w0, h[0][d]);
                h[0][d] = fmaf(xa.y, w1, h[0][d]);
                h[1][d] = fmaf(xb.x, w0, h[1][d]);
                h[1][d] = fmaf(xb.y, w1, h[1][d]);
            }
        }
        // 4-stage butterfly within each 16-lane half (80 shfl total)
        #pragma unroll
        for (int m = 0; m < 2; m++)
            #pragma unroll
            for (int d = 0; d < CD; d++)
                #pragma unroll
                for (int off = 8; off > 0; off >>= 1)
                    h[m][d] += __shfl_xor_sync(FULL, h[m][d], off);

        // lane hl==d picks up dim d
        float ra = 0.f, rb = 0.f;
        #pragma unroll
        for (int d = 0; d < CD; d++)
            if (hl == d) { ra = h[0][d]; rb = h[1][d]; }
        float bi = (hl < CD) ? bis[hl] : 0.f;
        ra += bi; rb += bi;

        const int row_a = row0 + 2 * half;   // this half's even row
        // ---- LFQ pipeline: ra carries rows {0,2}, rb rows {1,3} ----
        float qo_a = 0.f, qo_b = 0.f, iv_a = 0.f, iv_b = 0.f;

        #pragma unroll
        for (int q = 0; q < NQ; q++) {
            const float scale = 1.0f / (float)(1 << q);

            #define QSTEP(R, QO, IV, ROW)                                           \
            {                                                                       \
                bool pos = (R) > 0.f;                                               \
                unsigned bl = __ballot_sync(FULL, pos);                             \
                int idx = (int)(__brev((bl >> (half * 16)) & 0x3FFu) >> 22);        \
                if (hl == q) (IV) = (float)idx;                                     \
                float qv = pos ? scale : -scale;                                    \
                float dlt = (R) - qv;                                               \
                if (hl < CD) {                                                      \
                    float a = 400.f * scale * (R);                                  \
                    float t = fabsf(a);                                             \
                    float e = __expf(-t);                                           \
                    float inv = __fdividef(1.f, 1.f + e);                           \
                    float p = (a > 0.f) ? inv : e * inv;                            \
                    commit[q] += dlt * dlt;                                         \
                    psent[q] += __logf(1.f + e) + t * e * inv;                      \
                    g_ptab[((size_t)q * NROWS + (ROW)) * CD + hl] = p;              \
                }                                                                   \
                (R) = dlt;                                                          \
                (QO) += qv;                                                         \
            }

            QSTEP(ra, qo_a, iv_a, row_a)
            QSTEP(rb, qo_b, iv_b, row_a + 1)
            #undef QSTEP
        }

        // ---- indices ----
        if (hl < NQ) {
            out_idx[(size_t)row_a * NQ + hl]       = iv_a;
            out_idx[(size_t)(row_a + 1) * NQ + hl] = iv_b;
        }

        // ---- out = qo @ w_out + b_out ----
        float* outp = out + (size_t)row0 * DIMV;
        #pragma unroll
        for (int pr = 0; pr < 2; pr++) {     // pr: row pair (2pr, 2pr+1)
            float sa[CD], sb[CD];
            #pragma unroll
            for (int d = 0; d < CD; d++) {
                sa[d] = __shfl_sync(FULL, qo_a, pr * 16 + d);
                sb[d] = __shfl_sync(FULL, qo_b, pr * 16 + d);
            }
            #pragma unroll
            for (int k = 0; k < 4; k++) {
                int j4 = k * 32 + lane;
                float4 b4 = ((const float4*)bs)[j4];
                float4 aA = b4, aB = b4;
                #pragma unroll
                for (int d = 0; d < CD; d++) {
                    float4 w4 = ((const float4*)wos)[d * 128 + j4];
                    aA.x = fmaf(sa[d], w4.x, aA.x);
                    aA.y = fmaf(sa[d], w4.y, aA.y);
                    aA.z = fmaf(sa[d], w4.z, aA.z);
                    aA.w = fmaf(sa[d], w4.w, aA.w);
                    aB.x = fmaf(sb[d], w4.x, aB.x);
                    aB.y = fmaf(sb[d], w4.y, aB.y);
                    aB.z = fmaf(sb[d], w4.z, aB.z);
                    aB.w = fmaf(sb[d], w4.w, aB.w);
                }
                ((float4*)(outp + (size_t)(2 * pr) * DIMV))[j4] = aA;
                ((float4*)(outp + (size_t)(2 * pr + 1) * DIMV))[j4] = aB;
            }
        }
    }

    // per-warp loss partials -> one atomic per (warp, q)
    #pragma unroll
    for (int q = 0; q < NQ; q++) {
        float v = psent[q], c = commit[q];
        #pragma unroll
        for (int off = 16; off > 0; off >>= 1) {
            v += __shfl_xor_sync(FULL, v, off);
            c += __shfl_xor_sync(FULL, c, off);
        }
        if (lane == 0) {
            atomicAdd(&g_psent[q], v);
            atomicAdd(&g_commit[q], c);
        }
    }
}

// ---------------------------------------------------------------------------
// avg_prob accumulation: p_c = hi[c>>5] * lo[c&31]; 1 FFMA per (row, code)
#define CHUNK_ROWS 512
__global__ void __launch_bounds__(256) k_code() {
    const int q = blockIdx.x >> 7;       // 128 chunks per quantizer
    const int chunk = blockIdx.x & 127;
    const int row0 = chunk * CHUNK_ROWS;
    const int t = threadIdx.x;

    __shared__ float ps_s[16][CD];
    __shared__ __align__(16) float hl[16][64];   // [row][hi(0..31) | lo(32..63)]

    float acc0 = 0.f, acc1 = 0.f, acc2 = 0.f, acc3 = 0.f;
    const int hi_idx = t >> 3;
    const int lo0 = (t & 7) * 4;

    const float* pt = g_ptab + (size_t)q * NROWS * CD;

    for (int tile = 0; tile < CHUNK_ROWS / 16; tile++) {
        int r0 = row0 + tile * 16;
        if (t < 160) ps_s[t / CD][t % CD] = pt[(size_t)r0 * CD + t];
        __syncthreads();

        {
            int rl = t >> 4;
            int v0 = (t & 15) * 4;
            bool isHi = (v0 < 32);
            int dbase = isHi ? 0 : 5;
            int vb = isHi ? v0 : (v0 - 32);
            float p0 = ps_s[rl][dbase + 0], p1 = ps_s[rl][dbase + 1];
            float p2 = ps_s[rl][dbase + 2], p3 = ps_s[rl][dbase + 3];
            float p4 = ps_s[rl][dbase + 4];
            float n0 = 1.f - p0, n1 = 1.f - p1, n2 = 1.f - p2, n3 = 1.f - p3, n4 = 1.f - p4;
            float4 res;
            float* rp = &res.x;
            #pragma unroll
            for (int j = 0; j < 4; j++) {
                int v = vb + j;
                float val = ((v & 16) ? p0 : n0);
                val *= ((v & 8) ? p1 : n1);
                val *= ((v & 4) ? p2 : n2);
                val *= ((v & 2) ? p3 : n3);
                val *= ((v & 1) ? p4 : n4);
                rp[j] = val;
            }
            *(float4*)&hl[rl][v0] = res;
        }
        __syncthreads();

        #pragma unroll
        for (int rl = 0; rl < 16; rl++) {
            float hv = hl[rl][hi_idx];
            float4 l4 = *(const float4*)&hl[rl][32 + lo0];
            acc0 = fmaf(hv, l4.x, acc0);
            acc1 = fmaf(hv, l4.y, acc1);
            acc2 = fmaf(hv, l4.z, acc2);
            acc3 = fmaf(hv, l4.w, acc3);
        }
        __syncthreads();
    }

    int c = q * 1024 + hi_idx * 32 + lo0;
    atomicAdd(&g_codesum[c + 0], acc0);
    atomicAdd(&g_codesum[c + 1], acc1);
    atomicAdd(&g_codesum[c + 2], acc2);
    atomicAdd(&g_codesum[c + 3], acc3);
}

// ---------------------------------------------------------------------------
__global__ void k_fin(float* __restrict__ loss_out) {
    __shared__ float red[256];
    const int q = blockIdx.x;
    const int t = threadIdx.x;
    float e = 0.f;
    #pragma unroll
    for (int k = 0; k < 4; k++) {
        int c = k * 256 + t;
        float avg = g_codesum[q * 1024 + c] * (1.0f / (float)NROWS);
        e -= avg * __logf(fmaxf(avg, 1e-20f));
    }
    red[t] = e;
    __syncthreads();
    for (int s = 128; s > 0; s >>= 1) {
        if (t < s) red[t] += red[t + s];
        __syncthreads();
    }
    if (t == 0) {
        float per_sample = g_psent[q] * (1.0f / (float)NROWS);
        float ent_aux = per_sample - red[0];
        float commit = g_commit[q] * (1.0f / (float)(NROWS * CD));
        loss_out[q] = ent_aux * 0.1f + commit * 0.25f;
    }
}

// ---------------------------------------------------------------------------
extern "C" void kernel_launch(void* const* d_in, const int* in_sizes, int n_in,
                              void* d_out, int out_size) {
    const float* x     = (const float*)d_in[0];
    const float* w_in  = (const float*)d_in[1];
    const float* b_in  = (const float*)d_in[2];
    const float* w_out = (const float*)d_in[3];
    const float* b_out = (const float*)d_in[4];

    float* out  = (float*)d_out;
    float* idx  = out + OUT_ELEMS;
    float* loss = out + LOSS_OFFSET;

    k_zero<<<32, 256>>>();
    k_main<<<1024, 128>>>(x, w_in, b_in, w_out, b_out, out, idx);
    k_code<<<1024, 256>>>();
    k_fin<<<8, 256>>>(loss);
}